// round 13
// baseline (speedup 1.0000x reference)
#include <cuda_runtime.h>
#include <cuda_fp16.h>
#include <cstdint>
#include <math.h>

// Problem constants
#define T_TOK 4096
#define D_DIM 2048
#define FF_DIM 8192
#define E_EXP 16
#define CAP 640          // ceil(1.25 * 2 * 4096 / 16)

// ---------------------------------------------------------------------------
// Scratch (device globals — allocation-free kernel_launch)
// ---------------------------------------------------------------------------
__device__ __half g_Xe [(size_t)E_EXP * CAP * D_DIM];     // dispatched tokens fp16
__device__ __half g_h  [(size_t)E_EXP * CAP * FF_DIM];    // gelu(Xe@W1+b1) fp16
__device__ __half g_Ye [(size_t)E_EXP * CAP * D_DIM];     // expert outputs fp16
__device__ int    g_eidx[T_TOK * 2];
__device__ float  g_gate[T_TOK * 2];
__device__ int    g_pos [T_TOK * 2];

// ---------------------------------------------------------------------------
// Helpers
// ---------------------------------------------------------------------------
__device__ __forceinline__ float gelu_exact(float v) {
    return 0.5f * v * (1.0f + erff(v * 0.70710678118654752f));
}

__device__ __forceinline__ void cp_async16(uint32_t smem_addr, const void* gmem) {
    asm volatile("cp.async.cg.shared.global [%0], [%1], 16;\n" :: "r"(smem_addr), "l"(gmem));
}

__device__ __forceinline__ void ldsm_x4(uint32_t (&r)[4], uint32_t addr) {
    asm volatile("ldmatrix.sync.aligned.m8n8.x4.shared.b16 {%0,%1,%2,%3}, [%4];"
        : "=r"(r[0]), "=r"(r[1]), "=r"(r[2]), "=r"(r[3]) : "r"(addr));
}

__device__ __forceinline__ void ldsm_x4_trans(uint32_t (&r)[4], uint32_t addr) {
    asm volatile("ldmatrix.sync.aligned.m8n8.x4.trans.shared.b16 {%0,%1,%2,%3}, [%4];"
        : "=r"(r[0]), "=r"(r[1]), "=r"(r[2]), "=r"(r[3]) : "r"(addr));
}

__device__ __forceinline__ void mma_f16(float (&c)[4], const uint32_t (&a)[4],
                                        uint32_t b0, uint32_t b1) {
    asm volatile(
        "mma.sync.aligned.m16n8k16.row.col.f32.f16.f16.f32 "
        "{%0,%1,%2,%3}, {%4,%5,%6,%7}, {%8,%9}, {%0,%1,%2,%3};"
        : "+f"(c[0]), "+f"(c[1]), "+f"(c[2]), "+f"(c[3])
        : "r"(a[0]), "r"(a[1]), "r"(a[2]), "r"(a[3]), "r"(b0), "r"(b1));
}

// ---------------------------------------------------------------------------
// 1) Gating: one warp per token, coalesced Wg loads (proven in R11)
// ---------------------------------------------------------------------------
__global__ void gate_kernel(const float* __restrict__ x, const float* __restrict__ Wg) {
    int t = (blockIdx.x * blockDim.x + threadIdx.x) >> 5;
    int lane = threadIdx.x & 31;
    if (t >= T_TOK) return;
    const float* xr = x + (size_t)t * D_DIM;

    const int dl = lane >> 2;      // 0..7 : d-row within 8-row chunk
    const int part = lane & 3;     // 0..3 : which 4 experts

    float acc[4] = {0.f, 0.f, 0.f, 0.f};
    for (int d0 = 0; d0 < D_DIM; d0 += 8) {
        float xv = xr[d0 + dl];
        float4 w = *(const float4*)(Wg + (size_t)(d0 + dl) * E_EXP + part * 4);
        acc[0] += xv * w.x;
        acc[1] += xv * w.y;
        acc[2] += xv * w.z;
        acc[3] += xv * w.w;
    }
#pragma unroll
    for (int o = 4; o < 32; o <<= 1) {
#pragma unroll
        for (int q = 0; q < 4; q++)
            acc[q] += __shfl_xor_sync(0xffffffffu, acc[q], o);
    }
    float all16[E_EXP];
#pragma unroll
    for (int r = 0; r < 4; r++) {
#pragma unroll
        for (int q = 0; q < 4; q++)
            all16[r * 4 + q] = __shfl_sync(0xffffffffu, acc[q], r);
    }
    if (lane == 0) {
        int i1 = 0; float v1 = all16[0];
#pragma unroll
        for (int e = 1; e < E_EXP; e++) if (all16[e] > v1) { v1 = all16[e]; i1 = e; }
        int i2 = -1; float v2 = -1e30f;
#pragma unroll
        for (int e = 0; e < E_EXP; e++)
            if (e != i1 && all16[e] > v2) { v2 = all16[e]; i2 = e; }
        float r  = expf(v2 - v1);
        float g1 = 1.0f / (1.0f + r);
        float g2 = r * g1;
        g_eidx[t * 2 + 0] = i1;  g_eidx[t * 2 + 1] = i2;
        g_gate[t * 2 + 0] = g1;  g_gate[t * 2 + 1] = g2;
    }
}

// ---------------------------------------------------------------------------
// 2) Ordered capacity scan — PARALLEL (proven in R7)
// ---------------------------------------------------------------------------
__global__ void scan_kernel() {
    const int e = blockIdx.x;
    const int wid = threadIdx.x >> 5, lane = threadIdx.x & 31;
    __shared__ int wcnt[8], wbase[8];
    __shared__ int carry;
    if (threadIdx.x == 0) carry = 0;
    __syncthreads();

#pragma unroll
    for (int s = 0; s < 2; s++) {
        int cnt = 0;
        for (int t0 = wid * 512; t0 < wid * 512 + 512; t0 += 32) {
            bool m = (g_eidx[(t0 + lane) * 2 + s] == e);
            cnt += __popc(__ballot_sync(0xffffffffu, m));
        }
        if (lane == 0) wcnt[wid] = cnt;
        __syncthreads();
        if (threadIdx.x == 0) {
            int r = carry;
#pragma unroll
            for (int w = 0; w < 8; w++) { wbase[w] = r; r += wcnt[w]; }
            carry = r;
        }
        __syncthreads();
        int off = wbase[wid];
        for (int t0 = wid * 512; t0 < wid * 512 + 512; t0 += 32) {
            int t = t0 + lane;
            bool m = (g_eidx[t * 2 + s] == e);
            unsigned mask = __ballot_sync(0xffffffffu, m);
            if (m) g_pos[t * 2 + s] = off + __popc(mask & ((1u << lane) - 1u));
            off += __popc(mask);
        }
        __syncthreads();
    }
}

// ---------------------------------------------------------------------------
// 3) Dispatch: scatter token rows into Xe as fp16 (no memset needed)
// ---------------------------------------------------------------------------
__global__ void dispatch_kernel(const float* __restrict__ x) {
    int t = blockIdx.x;
    const float4* xr = (const float4*)(x + (size_t)t * D_DIM);
#pragma unroll
    for (int k = 0; k < 2; k++) {
        int p = g_pos[t * 2 + k];
        if (p < CAP) {
            int e = g_eidx[t * 2 + k];
            uint2* dst = (uint2*)(g_Xe + ((size_t)e * CAP + p) * D_DIM);
            for (int i = threadIdx.x; i < D_DIM / 4; i += blockDim.x) {
                float4 v = xr[i];
                __half2 a = __floats2half2_rn(v.x, v.y);
                __half2 b = __floats2half2_rn(v.z, v.w);
                uint2 u;
                u.x = *reinterpret_cast<uint32_t*>(&a);
                u.y = *reinterpret_cast<uint32_t*>(&b);
                dst[i] = u;
            }
        }
    }
}

// ---------------------------------------------------------------------------
// 4) Grouped GEMM, fp16 mma.sync.m16n8k16 + ldmatrix, fp32 accumulate.
//    Weights read as fp32 directly (no convert pass) with in-register
//    __floats2half2_rn (bit-identical to R12 => rel_err unchanged).
//    BK=64, 3-stage ring (halved sync frequency vs R12), 256 thr, 2 CTA/SM.
//    B staged in half-tiles (32 rows) of contiguous 16-float runs/thread:
//    4x LDG.128 + 2x STS.128 per half, conflict-free. A rows 72 halves
//    (144B), B rows 136 halves (272B) => conflict-free ldmatrix.
// ---------------------------------------------------------------------------
#define BK 64
#define SA 72            // halves per A smem row (144 B)
#define SB 136           // halves per B smem row (272 B)
#define A_BYTES (128 * SA * 2)        // 18432
#define B_BYTES (BK * SB * 2)         // 17408
#define STAGE_BYTES (A_BYTES + B_BYTES)
#define GEMM_SMEM (3 * STAGE_BYTES)   // 107520

template<int KDIM, int NDIM, bool DOGELU>
__global__ void __launch_bounds__(256, 2)
gemm_hmma(const __half* __restrict__ A, const float* __restrict__ Bw,
          const float* __restrict__ bias, __half* __restrict__ Cout) {
    constexpr int KT = KDIM / BK;
    extern __shared__ char smem[];
    const uint32_t smem_u32 = (uint32_t)__cvta_generic_to_shared(smem);
    const int tid = threadIdx.x, lane = tid & 31, wid = tid >> 5;
    const int mt = blockIdx.x, nt = blockIdx.y, e = blockIdx.z;
    const int wm = (wid & 1) * 64, wn = (wid >> 1) * 32;

    const __half* Ae = A + ((size_t)e * CAP + (size_t)mt * 128) * KDIM;
    const float*  Be = Bw + (size_t)e * KDIM * NDIM + (size_t)nt * 128;

    // A cp.async slots: 4 per thread (128 rows x 8 chunks of 8 halves)
    uint32_t sAoff[4], gAoff[4];
#pragma unroll
    for (int i = 0; i < 4; i++) {
        int u = tid + i * 256;
        int ar = u >> 3, ac = (u & 7) * 8;
        sAoff[i] = (ar * SA + ac) * 2;
        gAoff[i] = (uint32_t)ar * KDIM + ac;
    }

    // B mapping: half-tile = 32 rows x 128 cols fp32. 8 threads/row, each
    // thread 16 contiguous floats => 4 LDG.128 + 2 STS.128 (conflict-free).
    const int brow = tid >> 3;            // 0..31 within half
    const int bcol = (tid & 7) * 16;      // float column base
    const float* gBbase = Be + (size_t)brow * NDIM + bcol;
    const uint32_t sB0 = (uint32_t)A_BYTES + (brow * SB + bcol) * 2;

    // ldmatrix base offsets (bytes, within a stage)
    uint32_t aoff[4], boff[2];
#pragma unroll
    for (int fm = 0; fm < 4; fm++) {
        int row = wm + fm * 16 + (lane & 15);
        int kc  = (lane >> 4) * 8;
        aoff[fm] = (row * SA + kc) * 2;
    }
#pragma unroll
    for (int png = 0; png < 2; png++) {
        int kr = lane & 15;
        int nc = wn + png * 16 + (lane >> 4) * 8;
        boff[png] = (uint32_t)A_BYTES + (kr * SB + nc) * 2;
    }

    float acc[4][4][4];
#pragma unroll
    for (int i = 0; i < 4; i++)
#pragma unroll
        for (int j = 0; j < 4; j++)
#pragma unroll
            for (int q = 0; q < 4; q++) acc[i][j][q] = 0.0f;

    float4 rb[4];    // 16-float B register buffer (one half-tile slice)

    auto ldgB = [&](int kt, int h) {
        const float* p = gBbase + (size_t)(kt * BK + h * 32) * NDIM;
#pragma unroll
        for (int j = 0; j < 4; j++) rb[j] = ((const float4*)p)[j];
    };
    auto stsB = [&](int s, int h) {
        char* sm = smem + s * STAGE_BYTES + (h * 32 * SB) * 2;
        __half2 p0 = __floats2half2_rn(rb[0].x, rb[0].y);
        __half2 p1 = __floats2half2_rn(rb[0].z, rb[0].w);
        __half2 p2 = __floats2half2_rn(rb[1].x, rb[1].y);
        __half2 p3 = __floats2half2_rn(rb[1].z, rb[1].w);
        uint4 u0;
        u0.x = *reinterpret_cast<uint32_t*>(&p0);
        u0.y = *reinterpret_cast<uint32_t*>(&p1);
        u0.z = *reinterpret_cast<uint32_t*>(&p2);
        u0.w = *reinterpret_cast<uint32_t*>(&p3);
        *(uint4*)(sm + sB0) = u0;
        __half2 q0 = __floats2half2_rn(rb[2].x, rb[2].y);
        __half2 q1 = __floats2half2_rn(rb[2].z, rb[2].w);
        __half2 q2 = __floats2half2_rn(rb[3].x, rb[3].y);
        __half2 q3 = __floats2half2_rn(rb[3].z, rb[3].w);
        uint4 u1;
        u1.x = *reinterpret_cast<uint32_t*>(&q0);
        u1.y = *reinterpret_cast<uint32_t*>(&q1);
        u1.z = *reinterpret_cast<uint32_t*>(&q2);
        u1.w = *reinterpret_cast<uint32_t*>(&q3);
        *(uint4*)(sm + sB0 + 16) = u1;
    };
    auto cpA = [&](int s, int kt) {
        uint32_t sb = smem_u32 + s * STAGE_BYTES;
#pragma unroll
        for (int i = 0; i < 4; i++) cp_async16(sb + sAoff[i], Ae + gAoff[i] + kt * BK);
        asm volatile("cp.async.commit_group;" ::: "memory");
    };

    // prologue: A stages 0,1 async; B stage 0 fully staged; B(1).h0 in regs
    ldgB(0, 0);
    cpA(0, 0);
    if (KT > 1) cpA(1, 1);
    stsB(0, 0);
    ldgB(0, 1);
    stsB(0, 1);
    if (KT > 1) ldgB(1, 0);

    int s_cur = 0, s_nxt = 2;
    for (int kt = 0; kt < KT; kt++) {
        if (kt + 2 < KT) asm volatile("cp.async.wait_group 1;" ::: "memory");
        else             asm volatile("cp.async.wait_group 0;" ::: "memory");
        __syncthreads();
        if (kt + 2 < KT) cpA(s_nxt, kt + 2);

        uint32_t sb = smem_u32 + s_cur * STAGE_BYTES;
        const int s_b = (s_cur == 2) ? 0 : s_cur + 1;   // stage of kt+1
#pragma unroll
        for (int ks = 0; ks < 2; ks++) {
            uint32_t a[4][4], b[2][4];
#pragma unroll
            for (int fm = 0; fm < 4; fm++)
                ldsm_x4(a[fm], sb + aoff[fm] + ks * 32);
#pragma unroll
            for (int png = 0; png < 2; png++)
                ldsm_x4_trans(b[png], sb + boff[png] + ks * (16 * SB * 2));
#pragma unroll
            for (int fm = 0; fm < 4; fm++)
#pragma unroll
                for (int fn = 0; fn < 4; fn++)
                    mma_f16(acc[fm][fn], a[fm], b[fn >> 1][(fn & 1) * 2],
                            b[fn >> 1][(fn & 1) * 2 + 1]);
        }
        if (kt + 1 < KT) {
            stsB(s_b, 0);            // regs loaded at end of previous iter
            ldgB(kt + 1, 1);         // latency covered by ks=2,3 compute
        }
#pragma unroll
        for (int ks = 2; ks < 4; ks++) {
            uint32_t a[4][4], b[2][4];
#pragma unroll
            for (int fm = 0; fm < 4; fm++)
                ldsm_x4(a[fm], sb + aoff[fm] + ks * 32);
#pragma unroll
            for (int png = 0; png < 2; png++)
                ldsm_x4_trans(b[png], sb + boff[png] + ks * (16 * SB * 2));
#pragma unroll
            for (int fm = 0; fm < 4; fm++)
#pragma unroll
                for (int fn = 0; fn < 4; fn++)
                    mma_f16(acc[fm][fn], a[fm], b[fn >> 1][(fn & 1) * 2],
                            b[fn >> 1][(fn & 1) * 2 + 1]);
        }
        if (kt + 1 < KT) {
            stsB(s_b, 1);
            if (kt + 2 < KT) ldgB(kt + 2, 0);
        }
        s_cur = s_b;
        s_nxt = (s_nxt == 2) ? 0 : s_nxt + 1;
    }

    // bias for this warp's columns
    float bias0[4], bias1[4];
#pragma unroll
    for (int fn = 0; fn < 4; fn++) {
        int c = nt * 128 + wn + fn * 8 + (lane & 3) * 2;
        bias0[fn] = __ldg(bias + (size_t)e * NDIM + c);
        bias1[fn] = __ldg(bias + (size_t)e * NDIM + c + 1);
    }

    __syncthreads();   // mainloop smem dead -> reuse as epilogue staging

    __half* buf = (__half*)smem;          // [128][136] halves
#pragma unroll
    for (int fm = 0; fm < 4; fm++) {
#pragma unroll
        for (int fn = 0; fn < 4; fn++) {
            int row = wm + fm * 16 + (lane >> 2);
            int col = wn + fn * 8 + (lane & 3) * 2;
            float v0 = acc[fm][fn][0] + bias0[fn];
            float v1 = acc[fm][fn][1] + bias1[fn];
            float v2 = acc[fm][fn][2] + bias0[fn];
            float v3 = acc[fm][fn][3] + bias1[fn];
            if (DOGELU) {
                v0 = gelu_exact(v0); v1 = gelu_exact(v1);
                v2 = gelu_exact(v2); v3 = gelu_exact(v3);
            }
            __half2 p0 = __floats2half2_rn(v0, v1);
            __half2 p1 = __floats2half2_rn(v2, v3);
            *(uint32_t*)(buf + row * 136 + col)       = *reinterpret_cast<uint32_t*>(&p0);
            *(uint32_t*)(buf + (row + 8) * 136 + col) = *reinterpret_cast<uint32_t*>(&p1);
        }
    }
    __syncthreads();
    __half* Ce = Cout + ((size_t)e * CAP + (size_t)mt * 128) * NDIM
               + (size_t)nt * 128;
#pragma unroll
    for (int i = tid; i < 2048; i += 256) {     // 128 rows x 16 uint4
        int rr = i >> 4, cc = i & 15;
        uint4 v = *(const uint4*)(buf + rr * 136 + cc * 8);
        *(uint4*)(Ce + (size_t)rr * NDIM + cc * 8) = v;
    }
}

// ---------------------------------------------------------------------------
// 5) Combine: Ye is fp16
// ---------------------------------------------------------------------------
__global__ void combine_kernel(float* __restrict__ out) {
    int t = blockIdx.x;
    int e0 = g_eidx[t * 2 + 0], e1 = g_eidx[t * 2 + 1];
    int p0 = g_pos[t * 2 + 0],  p1 = g_pos[t * 2 + 1];
    float g0 = (p0 < CAP) ? g_gate[t * 2 + 0] : 0.0f;
    float g1 = (p1 < CAP) ? g_gate[t * 2 + 1] : 0.0f;
    p0 = min(p0, CAP - 1);
    p1 = min(p1, CAP - 1);
    const uint2* y0 = (const uint2*)(g_Ye + ((size_t)e0 * CAP + p0) * D_DIM);
    const uint2* y1 = (const uint2*)(g_Ye + ((size_t)e1 * CAP + p1) * D_DIM);
    float4* o = (float4*)(out + (size_t)t * D_DIM);
    for (int i = threadIdx.x; i < D_DIM / 4; i += blockDim.x) {
        uint2 ua = y0[i], ub = y1[i];
        float2 a0 = __half22float2(*reinterpret_cast<__half2*>(&ua.x));
        float2 a1 = __half22float2(*reinterpret_cast<__half2*>(&ua.y));
        float2 b0 = __half22float2(*reinterpret_cast<__half2*>(&ub.x));
        float2 b1 = __half22float2(*reinterpret_cast<__half2*>(&ub.y));
        float4 rv;
        rv.x = g0 * a0.x + g1 * b0.x;
        rv.y = g0 * a0.y + g1 * b0.y;
        rv.z = g0 * a1.x + g1 * b1.x;
        rv.w = g0 * a1.y + g1 * b1.y;
        o[i] = rv;
    }
}

// ---------------------------------------------------------------------------
// kernel_launch — single stream, no converts: GEMMs read fp32 weights.
// ---------------------------------------------------------------------------
extern "C" void kernel_launch(void* const* d_in, const int* in_sizes, int n_in,
                              void* d_out, int out_size) {
    const float* x  = (const float*)d_in[0];
    const float* Wg = (const float*)d_in[1];
    const float* W1 = (const float*)d_in[2];
    const float* b1 = (const float*)d_in[3];
    const float* W2 = (const float*)d_in[4];
    const float* b2 = (const float*)d_in[5];
    float* out = (float*)d_out;

    void *xe_p, *h_p, *ye_p;
    cudaGetSymbolAddress(&xe_p, g_Xe);
    cudaGetSymbolAddress(&h_p,  g_h);
    cudaGetSymbolAddress(&ye_p, g_Ye);

    cudaFuncSetAttribute(gemm_hmma<D_DIM, FF_DIM, true >,
                         cudaFuncAttributeMaxDynamicSharedMemorySize, GEMM_SMEM);
    cudaFuncSetAttribute(gemm_hmma<FF_DIM, D_DIM, false>,
                         cudaFuncAttributeMaxDynamicSharedMemorySize, GEMM_SMEM);

    gate_kernel<<<T_TOK / 8, 256>>>(x, Wg);
    scan_kernel<<<E_EXP, 256>>>();
    dispatch_kernel<<<T_TOK, 256>>>(x);

    gemm_hmma<D_DIM, FF_DIM, true ><<<dim3(CAP / 128, FF_DIM / 128, E_EXP),
                                      256, GEMM_SMEM>>>(
        (const __half*)xe_p, W1, b1, (__half*)h_p);

    gemm_hmma<FF_DIM, D_DIM, false><<<dim3(CAP / 128, D_DIM / 128, E_EXP),
                                      256, GEMM_SMEM>>>(
        (const __half*)h_p, W2, b2, (__half*)ye_p);

    combine_kernel<<<T_TOK, 256>>>(out);
}

// round 15
// speedup vs baseline: 1.3931x; 1.3931x over previous
#include <cuda_runtime.h>
#include <cuda_fp16.h>
#include <cstdint>
#include <math.h>

// Problem constants
#define T_TOK 4096
#define D_DIM 2048
#define FF_DIM 8192
#define E_EXP 16
#define CAP 640          // ceil(1.25 * 2 * 4096 / 16)

// ---------------------------------------------------------------------------
// Scratch (device globals — allocation-free kernel_launch)
// ---------------------------------------------------------------------------
__device__ __half g_Xe [(size_t)E_EXP * CAP * D_DIM];     // dispatched tokens fp16
__device__ __half g_h  [(size_t)E_EXP * CAP * FF_DIM];    // gelu(Xe@W1+b1) fp16
__device__ __half g_Ye [(size_t)E_EXP * CAP * D_DIM];     // expert outputs fp16
__device__ int    g_eidx[T_TOK * 2];
__device__ float  g_gate[T_TOK * 2];
__device__ int    g_pos [T_TOK * 2];
__device__ int    g_cnt [E_EXP];                          // per-expert row count

// ---------------------------------------------------------------------------
// Helpers
// ---------------------------------------------------------------------------
__device__ __forceinline__ float gelu_exact(float v) {
    return 0.5f * v * (1.0f + erff(v * 0.70710678118654752f));
}

__device__ __forceinline__ void cp_async16(uint32_t smem_addr, const void* gmem) {
    asm volatile("cp.async.cg.shared.global [%0], [%1], 16;\n" :: "r"(smem_addr), "l"(gmem));
}

__device__ __forceinline__ void ldsm_x4(uint32_t (&r)[4], uint32_t addr) {
    asm volatile("ldmatrix.sync.aligned.m8n8.x4.shared.b16 {%0,%1,%2,%3}, [%4];"
        : "=r"(r[0]), "=r"(r[1]), "=r"(r[2]), "=r"(r[3]) : "r"(addr));
}

__device__ __forceinline__ void ldsm_x4_trans(uint32_t (&r)[4], uint32_t addr) {
    asm volatile("ldmatrix.sync.aligned.m8n8.x4.trans.shared.b16 {%0,%1,%2,%3}, [%4];"
        : "=r"(r[0]), "=r"(r[1]), "=r"(r[2]), "=r"(r[3]) : "r"(addr));
}

__device__ __forceinline__ void mma_f16(float (&c)[4], const uint32_t (&a)[4],
                                        uint32_t b0, uint32_t b1) {
    asm volatile(
        "mma.sync.aligned.m16n8k16.row.col.f32.f16.f16.f32 "
        "{%0,%1,%2,%3}, {%4,%5,%6,%7}, {%8,%9}, {%0,%1,%2,%3};"
        : "+f"(c[0]), "+f"(c[1]), "+f"(c[2]), "+f"(c[3])
        : "r"(a[0]), "r"(a[1]), "r"(a[2]), "r"(a[3]), "r"(b0), "r"(b1));
}

// ---------------------------------------------------------------------------
// 1) Gating: one warp per token, coalesced Wg loads (proven in R11)
// ---------------------------------------------------------------------------
__global__ void gate_kernel(const float* __restrict__ x, const float* __restrict__ Wg) {
    int t = (blockIdx.x * blockDim.x + threadIdx.x) >> 5;
    int lane = threadIdx.x & 31;
    if (t >= T_TOK) return;
    const float* xr = x + (size_t)t * D_DIM;

    const int dl = lane >> 2;      // 0..7 : d-row within 8-row chunk
    const int part = lane & 3;     // 0..3 : which 4 experts

    float acc[4] = {0.f, 0.f, 0.f, 0.f};
    for (int d0 = 0; d0 < D_DIM; d0 += 8) {
        float xv = xr[d0 + dl];
        float4 w = *(const float4*)(Wg + (size_t)(d0 + dl) * E_EXP + part * 4);
        acc[0] += xv * w.x;
        acc[1] += xv * w.y;
        acc[2] += xv * w.z;
        acc[3] += xv * w.w;
    }
#pragma unroll
    for (int o = 4; o < 32; o <<= 1) {
#pragma unroll
        for (int q = 0; q < 4; q++)
            acc[q] += __shfl_xor_sync(0xffffffffu, acc[q], o);
    }
    float all16[E_EXP];
#pragma unroll
    for (int r = 0; r < 4; r++) {
#pragma unroll
        for (int q = 0; q < 4; q++)
            all16[r * 4 + q] = __shfl_sync(0xffffffffu, acc[q], r);
    }
    if (lane == 0) {
        int i1 = 0; float v1 = all16[0];
#pragma unroll
        for (int e = 1; e < E_EXP; e++) if (all16[e] > v1) { v1 = all16[e]; i1 = e; }
        int i2 = -1; float v2 = -1e30f;
#pragma unroll
        for (int e = 0; e < E_EXP; e++)
            if (e != i1 && all16[e] > v2) { v2 = all16[e]; i2 = e; }
        float r  = expf(v2 - v1);
        float g1 = 1.0f / (1.0f + r);
        float g2 = r * g1;
        g_eidx[t * 2 + 0] = i1;  g_eidx[t * 2 + 1] = i2;
        g_gate[t * 2 + 0] = g1;  g_gate[t * 2 + 1] = g2;
    }
}

// ---------------------------------------------------------------------------
// 2) Ordered capacity scan — PARALLEL (proven in R7); also publishes the
//    per-expert total count for GEMM tile skipping.
// ---------------------------------------------------------------------------
__global__ void scan_kernel() {
    const int e = blockIdx.x;
    const int wid = threadIdx.x >> 5, lane = threadIdx.x & 31;
    __shared__ int wcnt[8], wbase[8];
    __shared__ int carry;
    if (threadIdx.x == 0) carry = 0;
    __syncthreads();

#pragma unroll
    for (int s = 0; s < 2; s++) {
        int cnt = 0;
        for (int t0 = wid * 512; t0 < wid * 512 + 512; t0 += 32) {
            bool m = (g_eidx[(t0 + lane) * 2 + s] == e);
            cnt += __popc(__ballot_sync(0xffffffffu, m));
        }
        if (lane == 0) wcnt[wid] = cnt;
        __syncthreads();
        if (threadIdx.x == 0) {
            int r = carry;
#pragma unroll
            for (int w = 0; w < 8; w++) { wbase[w] = r; r += wcnt[w]; }
            carry = r;
        }
        __syncthreads();
        int off = wbase[wid];
        for (int t0 = wid * 512; t0 < wid * 512 + 512; t0 += 32) {
            int t = t0 + lane;
            bool m = (g_eidx[t * 2 + s] == e);
            unsigned mask = __ballot_sync(0xffffffffu, m);
            if (m) g_pos[t * 2 + s] = off + __popc(mask & ((1u << lane) - 1u));
            off += __popc(mask);
        }
        __syncthreads();
    }
    if (threadIdx.x == 0) g_cnt[e] = (carry < CAP) ? carry : CAP;
}

// ---------------------------------------------------------------------------
// 3) Dispatch: scatter token rows into Xe as fp16 (no memset needed)
// ---------------------------------------------------------------------------
__global__ void dispatch_kernel(const float* __restrict__ x) {
    int t = blockIdx.x;
    const float4* xr = (const float4*)(x + (size_t)t * D_DIM);
#pragma unroll
    for (int k = 0; k < 2; k++) {
        int p = g_pos[t * 2 + k];
        if (p < CAP) {
            int e = g_eidx[t * 2 + k];
            uint2* dst = (uint2*)(g_Xe + ((size_t)e * CAP + p) * D_DIM);
            for (int i = threadIdx.x; i < D_DIM / 4; i += blockDim.x) {
                float4 v = xr[i];
                __half2 a = __floats2half2_rn(v.x, v.y);
                __half2 b = __floats2half2_rn(v.z, v.w);
                uint2 u;
                u.x = *reinterpret_cast<uint32_t*>(&a);
                u.y = *reinterpret_cast<uint32_t*>(&b);
                dst[i] = u;
            }
        }
    }
}

// ---------------------------------------------------------------------------
// 4) Grouped GEMM — EXACT R12 kernel (proven fastest) + count-based tile
//    skip: CTAs whose 128-row tile lies entirely above this expert's row
//    count exit immediately (rows >= cnt are never read downstream).
//    Weights read as fp32 directly; in-register __floats2half2_rn.
//    BM=BN=128, BK=32, 4-stage ring, 256 thr, 2 CTA/SM.
// ---------------------------------------------------------------------------
#define BK 32
#define SA 40            // halves per A smem row (80 B)
#define SB 136           // halves per B smem row (272 B)
#define A_BYTES (128 * SA * 2)        // 10240
#define B_BYTES (BK * SB * 2)         //  8704
#define STAGE_BYTES (A_BYTES + B_BYTES)
#define GEMM_SMEM (4 * STAGE_BYTES)   // 75776

template<int KDIM, int NDIM, bool DOGELU>
__global__ void __launch_bounds__(256, 2)
gemm_hmma(const __half* __restrict__ A, const float* __restrict__ Bw,
          const float* __restrict__ bias, __half* __restrict__ Cout) {
    constexpr int KT = KDIM / BK;
    extern __shared__ char smem[];
    const uint32_t smem_u32 = (uint32_t)__cvta_generic_to_shared(smem);
    const int tid = threadIdx.x, lane = tid & 31, wid = tid >> 5;
    const int mt = blockIdx.x, nt = blockIdx.y, e = blockIdx.z;

    if (mt * 128 >= g_cnt[e]) return;   // tile entirely above used rows

    const int wm = (wid & 1) * 64, wn = (wid >> 1) * 32;

    const __half* Ae = A + ((size_t)e * CAP + (size_t)mt * 128) * KDIM;
    const float*  Be = Bw + (size_t)e * KDIM * NDIM + (size_t)nt * 128;

    // A cp.async slots: 2 per thread (128 rows x 4 chunks of 8 halves)
    uint32_t sAoff[2];
    const __half* gA[2];
#pragma unroll
    for (int i = 0; i < 2; i++) {
        int u = tid + i * 256;
        int ar = u >> 2, ac = u & 3;
        sAoff[i] = (ar * SA + ac * 8) * 2;
        gA[i] = Ae + (size_t)ar * KDIM + ac * 8;
    }

    // B fp32 load/store mapping (R12-proven): row br = tid>>3, col base
    // c4 = (tid&7)*4 floats; j-loop strides 32 floats.
    const int br = tid >> 3, c4 = (tid & 7) * 4;
    const float* gBrow = Be + (size_t)br * NDIM + c4;
    uint32_t sBbase = (uint32_t)A_BYTES + (br * SB + c4) * 2;

    // ldmatrix base offsets (bytes, within a stage)
    uint32_t aoff[4], boff[2];
#pragma unroll
    for (int fm = 0; fm < 4; fm++) {
        int row = wm + fm * 16 + (lane & 15);
        int kc  = (lane >> 4) * 8;
        aoff[fm] = (row * SA + kc) * 2;
    }
#pragma unroll
    for (int png = 0; png < 2; png++) {
        int kr = lane & 15;
        int nc = wn + png * 16 + (lane >> 4) * 8;
        boff[png] = (uint32_t)A_BYTES + (kr * SB + nc) * 2;
    }

    float acc[4][4][4];
#pragma unroll
    for (int i = 0; i < 4; i++)
#pragma unroll
        for (int j = 0; j < 4; j++)
#pragma unroll
            for (int q = 0; q < 4; q++) acc[i][j][q] = 0.0f;

    float4 rb[4];    // register B buffer (one 32x128 fp32 tile / 256 threads)

    auto ldgB = [&](int kt) {
#pragma unroll
        for (int j = 0; j < 4; j++)
            rb[j] = *(const float4*)(gBrow + (size_t)kt * BK * NDIM + j * 32);
    };
    auto stsB = [&](int s) {
        char* sm = smem + s * STAGE_BYTES;
#pragma unroll
        for (int j = 0; j < 4; j++) {
            __half2 p0 = __floats2half2_rn(rb[j].x, rb[j].y);
            __half2 p1 = __floats2half2_rn(rb[j].z, rb[j].w);
            uint2 u;
            u.x = *reinterpret_cast<uint32_t*>(&p0);
            u.y = *reinterpret_cast<uint32_t*>(&p1);
            *(uint2*)(sm + sBbase + j * 64) = u;   // j*32 halves = 64 bytes
        }
    };
    auto cpA = [&](int s, int kt) {
        uint32_t sb = smem_u32 + s * STAGE_BYTES;
#pragma unroll
        for (int i = 0; i < 2; i++) cp_async16(sb + sAoff[i], gA[i] + kt * BK);
        asm volatile("cp.async.commit_group;" ::: "memory");
    };

    // prologue: B stage0 synchronously; A stages 0..2 async
    ldgB(0);
    cpA(0, 0);
    if (KT > 1) cpA(1, 1);
    if (KT > 2) cpA(2, 2);
    stsB(0);
    if (KT > 1) ldgB(1);

    for (int kt = 0; kt < KT; kt++) {
        if (kt + 3 < KT)      asm volatile("cp.async.wait_group 2;" ::: "memory");
        else if (kt + 2 < KT) asm volatile("cp.async.wait_group 1;" ::: "memory");
        else                  asm volatile("cp.async.wait_group 0;" ::: "memory");
        __syncthreads();
        if (kt + 3 < KT) cpA((kt + 3) & 3, kt + 3);

        uint32_t sb = smem_u32 + (kt & 3) * STAGE_BYTES;
#pragma unroll
        for (int ks = 0; ks < 2; ks++) {
            uint32_t a[4][4], b[2][4];
#pragma unroll
            for (int fm = 0; fm < 4; fm++)
                ldsm_x4(a[fm], sb + aoff[fm] + ks * 32);            // +16 halves in k
#pragma unroll
            for (int png = 0; png < 2; png++)
                ldsm_x4_trans(b[png], sb + boff[png] + ks * (16 * SB * 2));
#pragma unroll
            for (int fm = 0; fm < 4; fm++)
#pragma unroll
                for (int fn = 0; fn < 4; fn++)
                    mma_f16(acc[fm][fn], a[fm], b[fn >> 1][(fn & 1) * 2],
                            b[fn >> 1][(fn & 1) * 2 + 1]);
        }
        if (kt + 1 < KT) {
            stsB((kt + 1) & 3);          // regs loaded one iteration ago
            if (kt + 2 < KT) ldgB(kt + 2);
        }
    }

    // bias for this warp's columns
    float bias0[4], bias1[4];
#pragma unroll
    for (int fn = 0; fn < 4; fn++) {
        int c = nt * 128 + wn + fn * 8 + (lane & 3) * 2;
        bias0[fn] = __ldg(bias + (size_t)e * NDIM + c);
        bias1[fn] = __ldg(bias + (size_t)e * NDIM + c + 1);
    }

    __syncthreads();   // mainloop smem dead -> reuse as epilogue staging

    __half* buf = (__half*)smem;          // [128][136] halves
#pragma unroll
    for (int fm = 0; fm < 4; fm++) {
#pragma unroll
        for (int fn = 0; fn < 4; fn++) {
            int row = wm + fm * 16 + (lane >> 2);
            int col = wn + fn * 8 + (lane & 3) * 2;
            float v0 = acc[fm][fn][0] + bias0[fn];
            float v1 = acc[fm][fn][1] + bias1[fn];
            float v2 = acc[fm][fn][2] + bias0[fn];
            float v3 = acc[fm][fn][3] + bias1[fn];
            if (DOGELU) {
                v0 = gelu_exact(v0); v1 = gelu_exact(v1);
                v2 = gelu_exact(v2); v3 = gelu_exact(v3);
            }
            __half2 p0 = __floats2half2_rn(v0, v1);
            __half2 p1 = __floats2half2_rn(v2, v3);
            *(uint32_t*)(buf + row * 136 + col)       = *reinterpret_cast<uint32_t*>(&p0);
            *(uint32_t*)(buf + (row + 8) * 136 + col) = *reinterpret_cast<uint32_t*>(&p1);
        }
    }
    __syncthreads();
    __half* Ce = Cout + ((size_t)e * CAP + (size_t)mt * 128) * NDIM
               + (size_t)nt * 128;
#pragma unroll
    for (int i = tid; i < 2048; i += 256) {     // 128 rows x 16 uint4
        int rr = i >> 4, cc = i & 15;
        uint4 v = *(const uint4*)(buf + rr * 136 + cc * 8);
        *(uint4*)(Ce + (size_t)rr * NDIM + cc * 8) = v;
    }
}

// ---------------------------------------------------------------------------
// 5) Combine: Ye is fp16
// ---------------------------------------------------------------------------
__global__ void combine_kernel(float* __restrict__ out) {
    int t = blockIdx.x;
    int e0 = g_eidx[t * 2 + 0], e1 = g_eidx[t * 2 + 1];
    int p0 = g_pos[t * 2 + 0],  p1 = g_pos[t * 2 + 1];
    float g0 = (p0 < CAP) ? g_gate[t * 2 + 0] : 0.0f;
    float g1 = (p1 < CAP) ? g_gate[t * 2 + 1] : 0.0f;
    p0 = min(p0, CAP - 1);
    p1 = min(p1, CAP - 1);
    const uint2* y0 = (const uint2*)(g_Ye + ((size_t)e0 * CAP + p0) * D_DIM);
    const uint2* y1 = (const uint2*)(g_Ye + ((size_t)e1 * CAP + p1) * D_DIM);
    float4* o = (float4*)(out + (size_t)t * D_DIM);
    for (int i = threadIdx.x; i < D_DIM / 4; i += blockDim.x) {
        uint2 ua = y0[i], ub = y1[i];
        float2 a0 = __half22float2(*reinterpret_cast<__half2*>(&ua.x));
        float2 a1 = __half22float2(*reinterpret_cast<__half2*>(&ua.y));
        float2 b0 = __half22float2(*reinterpret_cast<__half2*>(&ub.x));
        float2 b1 = __half22float2(*reinterpret_cast<__half2*>(&ub.y));
        float4 rv;
        rv.x = g0 * a0.x + g1 * b0.x;
        rv.y = g0 * a0.y + g1 * b0.y;
        rv.z = g0 * a1.x + g1 * b1.x;
        rv.w = g0 * a1.y + g1 * b1.y;
        o[i] = rv;
    }
}

// ---------------------------------------------------------------------------
// kernel_launch — single stream, no converts: GEMMs read fp32 weights.
// ---------------------------------------------------------------------------
extern "C" void kernel_launch(void* const* d_in, const int* in_sizes, int n_in,
                              void* d_out, int out_size) {
    const float* x  = (const float*)d_in[0];
    const float* Wg = (const float*)d_in[1];
    const float* W1 = (const float*)d_in[2];
    const float* b1 = (const float*)d_in[3];
    const float* W2 = (const float*)d_in[4];
    const float* b2 = (const float*)d_in[5];
    float* out = (float*)d_out;

    void *xe_p, *h_p, *ye_p;
    cudaGetSymbolAddress(&xe_p, g_Xe);
    cudaGetSymbolAddress(&h_p,  g_h);
    cudaGetSymbolAddress(&ye_p, g_Ye);

    cudaFuncSetAttribute(gemm_hmma<D_DIM, FF_DIM, true >,
                         cudaFuncAttributeMaxDynamicSharedMemorySize, GEMM_SMEM);
    cudaFuncSetAttribute(gemm_hmma<FF_DIM, D_DIM, false>,
                         cudaFuncAttributeMaxDynamicSharedMemorySize, GEMM_SMEM);

    gate_kernel<<<T_TOK / 8, 256>>>(x, Wg);
    scan_kernel<<<E_EXP, 256>>>();
    dispatch_kernel<<<T_TOK, 256>>>(x);

    gemm_hmma<D_DIM, FF_DIM, true ><<<dim3(CAP / 128, FF_DIM / 128, E_EXP),
                                      256, GEMM_SMEM>>>(
        (const __half*)xe_p, W1, b1, (__half*)h_p);

    gemm_hmma<FF_DIM, D_DIM, false><<<dim3(CAP / 128, D_DIM / 128, E_EXP),
                                      256, GEMM_SMEM>>>(
        (const __half*)h_p, W2, b2, (__half*)ye_p);

    combine_kernel<<<T_TOK, 256>>>(out);
}

// round 16
// speedup vs baseline: 1.4367x; 1.0313x over previous
#include <cuda_runtime.h>
#include <cuda_fp16.h>
#include <cstdint>
#include <math.h>

// Problem constants
#define T_TOK 4096
#define D_DIM 2048
#define FF_DIM 8192
#define E_EXP 16
#define CAP 640          // ceil(1.25 * 2 * 4096 / 16)

// ---------------------------------------------------------------------------
// Scratch (device globals — allocation-free kernel_launch)
// ---------------------------------------------------------------------------
__device__ __half g_Xe [(size_t)E_EXP * CAP * D_DIM];     // dispatched tokens fp16
__device__ __half g_h  [(size_t)E_EXP * CAP * FF_DIM];    // gelu(Xe@W1+b1) fp16
__device__ __half g_Ye [(size_t)E_EXP * CAP * D_DIM];     // expert outputs fp16
__device__ int    g_eidx[T_TOK * 2];
__device__ float  g_gate[T_TOK * 2];
__device__ int    g_pos [T_TOK * 2];
__device__ int    g_cnt [E_EXP];                          // per-expert row count

// ---------------------------------------------------------------------------
// Helpers
// ---------------------------------------------------------------------------
__device__ __forceinline__ float gelu_exact(float v) {
    return 0.5f * v * (1.0f + erff(v * 0.70710678118654752f));
}

__device__ __forceinline__ void cp_async16(uint32_t smem_addr, const void* gmem) {
    asm volatile("cp.async.cg.shared.global [%0], [%1], 16;\n" :: "r"(smem_addr), "l"(gmem));
}

// B weight load: fp32 vec4, L2-only (.cg) — keeps single-use weight stream
// out of the saturated L1/smem pipe.
__device__ __forceinline__ float4 ldg_cg_f4(const float* p) {
    float4 v;
    asm volatile("ld.global.cg.v4.f32 {%0,%1,%2,%3}, [%4];"
        : "=f"(v.x), "=f"(v.y), "=f"(v.z), "=f"(v.w) : "l"(p));
    return v;
}

__device__ __forceinline__ void ldsm_x4(uint32_t (&r)[4], uint32_t addr) {
    asm volatile("ldmatrix.sync.aligned.m8n8.x4.shared.b16 {%0,%1,%2,%3}, [%4];"
        : "=r"(r[0]), "=r"(r[1]), "=r"(r[2]), "=r"(r[3]) : "r"(addr));
}

__device__ __forceinline__ void ldsm_x4_trans(uint32_t (&r)[4], uint32_t addr) {
    asm volatile("ldmatrix.sync.aligned.m8n8.x4.trans.shared.b16 {%0,%1,%2,%3}, [%4];"
        : "=r"(r[0]), "=r"(r[1]), "=r"(r[2]), "=r"(r[3]) : "r"(addr));
}

__device__ __forceinline__ void mma_f16(float (&c)[4], const uint32_t (&a)[4],
                                        uint32_t b0, uint32_t b1) {
    asm volatile(
        "mma.sync.aligned.m16n8k16.row.col.f32.f16.f16.f32 "
        "{%0,%1,%2,%3}, {%4,%5,%6,%7}, {%8,%9}, {%0,%1,%2,%3};"
        : "+f"(c[0]), "+f"(c[1]), "+f"(c[2]), "+f"(c[3])
        : "r"(a[0]), "r"(a[1]), "r"(a[2]), "r"(a[3]), "r"(b0), "r"(b1));
}

// ---------------------------------------------------------------------------
// 1) Gating: one warp per token, coalesced Wg loads (proven in R11)
// ---------------------------------------------------------------------------
__global__ void gate_kernel(const float* __restrict__ x, const float* __restrict__ Wg) {
    int t = (blockIdx.x * blockDim.x + threadIdx.x) >> 5;
    int lane = threadIdx.x & 31;
    if (t >= T_TOK) return;
    const float* xr = x + (size_t)t * D_DIM;

    const int dl = lane >> 2;      // 0..7 : d-row within 8-row chunk
    const int part = lane & 3;     // 0..3 : which 4 experts

    float acc[4] = {0.f, 0.f, 0.f, 0.f};
    for (int d0 = 0; d0 < D_DIM; d0 += 8) {
        float xv = xr[d0 + dl];
        float4 w = *(const float4*)(Wg + (size_t)(d0 + dl) * E_EXP + part * 4);
        acc[0] += xv * w.x;
        acc[1] += xv * w.y;
        acc[2] += xv * w.z;
        acc[3] += xv * w.w;
    }
#pragma unroll
    for (int o = 4; o < 32; o <<= 1) {
#pragma unroll
        for (int q = 0; q < 4; q++)
            acc[q] += __shfl_xor_sync(0xffffffffu, acc[q], o);
    }
    float all16[E_EXP];
#pragma unroll
    for (int r = 0; r < 4; r++) {
#pragma unroll
        for (int q = 0; q < 4; q++)
            all16[r * 4 + q] = __shfl_sync(0xffffffffu, acc[q], r);
    }
    if (lane == 0) {
        int i1 = 0; float v1 = all16[0];
#pragma unroll
        for (int e = 1; e < E_EXP; e++) if (all16[e] > v1) { v1 = all16[e]; i1 = e; }
        int i2 = -1; float v2 = -1e30f;
#pragma unroll
        for (int e = 0; e < E_EXP; e++)
            if (e != i1 && all16[e] > v2) { v2 = all16[e]; i2 = e; }
        float r  = expf(v2 - v1);
        float g1 = 1.0f / (1.0f + r);
        float g2 = r * g1;
        g_eidx[t * 2 + 0] = i1;  g_eidx[t * 2 + 1] = i2;
        g_gate[t * 2 + 0] = g1;  g_gate[t * 2 + 1] = g2;
    }
}

// ---------------------------------------------------------------------------
// 2) Ordered capacity scan — PARALLEL (proven in R7); publishes per-expert
//    row counts for GEMM tile skipping.
// ---------------------------------------------------------------------------
__global__ void scan_kernel() {
    const int e = blockIdx.x;
    const int wid = threadIdx.x >> 5, lane = threadIdx.x & 31;
    __shared__ int wcnt[8], wbase[8];
    __shared__ int carry;
    if (threadIdx.x == 0) carry = 0;
    __syncthreads();

#pragma unroll
    for (int s = 0; s < 2; s++) {
        int cnt = 0;
        for (int t0 = wid * 512; t0 < wid * 512 + 512; t0 += 32) {
            bool m = (g_eidx[(t0 + lane) * 2 + s] == e);
            cnt += __popc(__ballot_sync(0xffffffffu, m));
        }
        if (lane == 0) wcnt[wid] = cnt;
        __syncthreads();
        if (threadIdx.x == 0) {
            int r = carry;
#pragma unroll
            for (int w = 0; w < 8; w++) { wbase[w] = r; r += wcnt[w]; }
            carry = r;
        }
        __syncthreads();
        int off = wbase[wid];
        for (int t0 = wid * 512; t0 < wid * 512 + 512; t0 += 32) {
            int t = t0 + lane;
            bool m = (g_eidx[t * 2 + s] == e);
            unsigned mask = __ballot_sync(0xffffffffu, m);
            if (m) g_pos[t * 2 + s] = off + __popc(mask & ((1u << lane) - 1u));
            off += __popc(mask);
        }
        __syncthreads();
    }
    if (threadIdx.x == 0) g_cnt[e] = (carry < CAP) ? carry : CAP;
}

// ---------------------------------------------------------------------------
// 3) Dispatch: scatter token rows into Xe as fp16 (no memset needed)
// ---------------------------------------------------------------------------
__global__ void dispatch_kernel(const float* __restrict__ x) {
    int t = blockIdx.x;
    const float4* xr = (const float4*)(x + (size_t)t * D_DIM);
#pragma unroll
    for (int k = 0; k < 2; k++) {
        int p = g_pos[t * 2 + k];
        if (p < CAP) {
            int e = g_eidx[t * 2 + k];
            uint2* dst = (uint2*)(g_Xe + ((size_t)e * CAP + p) * D_DIM);
            for (int i = threadIdx.x; i < D_DIM / 4; i += blockDim.x) {
                float4 v = xr[i];
                __half2 a = __floats2half2_rn(v.x, v.y);
                __half2 b = __floats2half2_rn(v.z, v.w);
                uint2 u;
                u.x = *reinterpret_cast<uint32_t*>(&a);
                u.y = *reinterpret_cast<uint32_t*>(&b);
                dst[i] = u;
            }
        }
    }
}

// ---------------------------------------------------------------------------
// 4) Grouped GEMM — R12/R15-proven kernel + count-based tile skip.
//    Weights read as fp32 directly via L2-only loads (ld.global.cg);
//    in-register __floats2half2_rn (bit-identical numerics).
//    BM=BN=128, BK=32, 4-stage ring, 256 thr, 2 CTA/SM.
// ---------------------------------------------------------------------------
#define BK 32
#define SA 40            // halves per A smem row (80 B)
#define SB 136           // halves per B smem row (272 B)
#define A_BYTES (128 * SA * 2)        // 10240
#define B_BYTES (BK * SB * 2)         //  8704
#define STAGE_BYTES (A_BYTES + B_BYTES)
#define GEMM_SMEM (4 * STAGE_BYTES)   // 75776

template<int KDIM, int NDIM, bool DOGELU>
__global__ void __launch_bounds__(256, 2)
gemm_hmma(const __half* __restrict__ A, const float* __restrict__ Bw,
          const float* __restrict__ bias, __half* __restrict__ Cout) {
    constexpr int KT = KDIM / BK;
    extern __shared__ char smem[];
    const uint32_t smem_u32 = (uint32_t)__cvta_generic_to_shared(smem);
    const int tid = threadIdx.x, lane = tid & 31, wid = tid >> 5;
    const int mt = blockIdx.x, nt = blockIdx.y, e = blockIdx.z;

    if (mt * 128 >= g_cnt[e]) return;   // tile entirely above used rows

    const int wm = (wid & 1) * 64, wn = (wid >> 1) * 32;

    const __half* Ae = A + ((size_t)e * CAP + (size_t)mt * 128) * KDIM;
    const float*  Be = Bw + (size_t)e * KDIM * NDIM + (size_t)nt * 128;

    // A cp.async slots: 2 per thread (128 rows x 4 chunks of 8 halves)
    uint32_t sAoff[2];
    const __half* gA[2];
#pragma unroll
    for (int i = 0; i < 2; i++) {
        int u = tid + i * 256;
        int ar = u >> 2, ac = u & 3;
        sAoff[i] = (ar * SA + ac * 8) * 2;
        gA[i] = Ae + (size_t)ar * KDIM + ac * 8;
    }

    // B fp32 load/store mapping (R12-proven): row br = tid>>3, col base
    // c4 = (tid&7)*4 floats; j-loop strides 32 floats.
    const int br = tid >> 3, c4 = (tid & 7) * 4;
    const float* gBrow = Be + (size_t)br * NDIM + c4;
    uint32_t sBbase = (uint32_t)A_BYTES + (br * SB + c4) * 2;

    // ldmatrix base offsets (bytes, within a stage)
    uint32_t aoff[4], boff[2];
#pragma unroll
    for (int fm = 0; fm < 4; fm++) {
        int row = wm + fm * 16 + (lane & 15);
        int kc  = (lane >> 4) * 8;
        aoff[fm] = (row * SA + kc) * 2;
    }
#pragma unroll
    for (int png = 0; png < 2; png++) {
        int kr = lane & 15;
        int nc = wn + png * 16 + (lane >> 4) * 8;
        boff[png] = (uint32_t)A_BYTES + (kr * SB + nc) * 2;
    }

    float acc[4][4][4];
#pragma unroll
    for (int i = 0; i < 4; i++)
#pragma unroll
        for (int j = 0; j < 4; j++)
#pragma unroll
            for (int q = 0; q < 4; q++) acc[i][j][q] = 0.0f;

    float4 rb[4];    // register B buffer (one 32x128 fp32 tile / 256 threads)

    auto ldgB = [&](int kt) {
#pragma unroll
        for (int j = 0; j < 4; j++)
            rb[j] = ldg_cg_f4(gBrow + (size_t)kt * BK * NDIM + j * 32);
    };
    auto stsB = [&](int s) {
        char* sm = smem + s * STAGE_BYTES;
#pragma unroll
        for (int j = 0; j < 4; j++) {
            __half2 p0 = __floats2half2_rn(rb[j].x, rb[j].y);
            __half2 p1 = __floats2half2_rn(rb[j].z, rb[j].w);
            uint2 u;
            u.x = *reinterpret_cast<uint32_t*>(&p0);
            u.y = *reinterpret_cast<uint32_t*>(&p1);
            *(uint2*)(sm + sBbase + j * 64) = u;   // j*32 halves = 64 bytes
        }
    };
    auto cpA = [&](int s, int kt) {
        uint32_t sb = smem_u32 + s * STAGE_BYTES;
#pragma unroll
        for (int i = 0; i < 2; i++) cp_async16(sb + sAoff[i], gA[i] + kt * BK);
        asm volatile("cp.async.commit_group;" ::: "memory");
    };

    // prologue: B stage0 synchronously; A stages 0..2 async
    ldgB(0);
    cpA(0, 0);
    if (KT > 1) cpA(1, 1);
    if (KT > 2) cpA(2, 2);
    stsB(0);
    if (KT > 1) ldgB(1);

    for (int kt = 0; kt < KT; kt++) {
        if (kt + 3 < KT)      asm volatile("cp.async.wait_group 2;" ::: "memory");
        else if (kt + 2 < KT) asm volatile("cp.async.wait_group 1;" ::: "memory");
        else                  asm volatile("cp.async.wait_group 0;" ::: "memory");
        __syncthreads();
        if (kt + 3 < KT) cpA((kt + 3) & 3, kt + 3);

        uint32_t sb = smem_u32 + (kt & 3) * STAGE_BYTES;
#pragma unroll
        for (int ks = 0; ks < 2; ks++) {
            uint32_t a[4][4], b[2][4];
#pragma unroll
            for (int fm = 0; fm < 4; fm++)
                ldsm_x4(a[fm], sb + aoff[fm] + ks * 32);            // +16 halves in k
#pragma unroll
            for (int png = 0; png < 2; png++)
                ldsm_x4_trans(b[png], sb + boff[png] + ks * (16 * SB * 2));
#pragma unroll
            for (int fm = 0; fm < 4; fm++)
#pragma unroll
                for (int fn = 0; fn < 4; fn++)
                    mma_f16(acc[fm][fn], a[fm], b[fn >> 1][(fn & 1) * 2],
                            b[fn >> 1][(fn & 1) * 2 + 1]);
        }
        if (kt + 1 < KT) {
            stsB((kt + 1) & 3);          // regs loaded one iteration ago
            if (kt + 2 < KT) ldgB(kt + 2);
        }
    }

    // bias for this warp's columns
    float bias0[4], bias1[4];
#pragma unroll
    for (int fn = 0; fn < 4; fn++) {
        int c = nt * 128 + wn + fn * 8 + (lane & 3) * 2;
        bias0[fn] = __ldg(bias + (size_t)e * NDIM + c);
        bias1[fn] = __ldg(bias + (size_t)e * NDIM + c + 1);
    }

    __syncthreads();   // mainloop smem dead -> reuse as epilogue staging

    __half* buf = (__half*)smem;          // [128][136] halves
#pragma unroll
    for (int fm = 0; fm < 4; fm++) {
#pragma unroll
        for (int fn = 0; fn < 4; fn++) {
            int row = wm + fm * 16 + (lane >> 2);
            int col = wn + fn * 8 + (lane & 3) * 2;
            float v0 = acc[fm][fn][0] + bias0[fn];
            float v1 = acc[fm][fn][1] + bias1[fn];
            float v2 = acc[fm][fn][2] + bias0[fn];
            float v3 = acc[fm][fn][3] + bias1[fn];
            if (DOGELU) {
                v0 = gelu_exact(v0); v1 = gelu_exact(v1);
                v2 = gelu_exact(v2); v3 = gelu_exact(v3);
            }
            __half2 p0 = __floats2half2_rn(v0, v1);
            __half2 p1 = __floats2half2_rn(v2, v3);
            *(uint32_t*)(buf + row * 136 + col)       = *reinterpret_cast<uint32_t*>(&p0);
            *(uint32_t*)(buf + (row + 8) * 136 + col) = *reinterpret_cast<uint32_t*>(&p1);
        }
    }
    __syncthreads();
    __half* Ce = Cout + ((size_t)e * CAP + (size_t)mt * 128) * NDIM
               + (size_t)nt * 128;
#pragma unroll
    for (int i = tid; i < 2048; i += 256) {     // 128 rows x 16 uint4
        int rr = i >> 4, cc = i & 15;
        uint4 v = *(const uint4*)(buf + rr * 136 + cc * 8);
        *(uint4*)(Ce + (size_t)rr * NDIM + cc * 8) = v;
    }
}

// ---------------------------------------------------------------------------
// 5) Combine: Ye is fp16
// ---------------------------------------------------------------------------
__global__ void combine_kernel(float* __restrict__ out) {
    int t = blockIdx.x;
    int e0 = g_eidx[t * 2 + 0], e1 = g_eidx[t * 2 + 1];
    int p0 = g_pos[t * 2 + 0],  p1 = g_pos[t * 2 + 1];
    float g0 = (p0 < CAP) ? g_gate[t * 2 + 0] : 0.0f;
    float g1 = (p1 < CAP) ? g_gate[t * 2 + 1] : 0.0f;
    p0 = min(p0, CAP - 1);
    p1 = min(p1, CAP - 1);
    const uint2* y0 = (const uint2*)(g_Ye + ((size_t)e0 * CAP + p0) * D_DIM);
    const uint2* y1 = (const uint2*)(g_Ye + ((size_t)e1 * CAP + p1) * D_DIM);
    float4* o = (float4*)(out + (size_t)t * D_DIM);
    for (int i = threadIdx.x; i < D_DIM / 4; i += blockDim.x) {
        uint2 ua = y0[i], ub = y1[i];
        float2 a0 = __half22float2(*reinterpret_cast<__half2*>(&ua.x));
        float2 a1 = __half22float2(*reinterpret_cast<__half2*>(&ua.y));
        float2 b0 = __half22float2(*reinterpret_cast<__half2*>(&ub.x));
        float2 b1 = __half22float2(*reinterpret_cast<__half2*>(&ub.y));
        float4 rv;
        rv.x = g0 * a0.x + g1 * b0.x;
        rv.y = g0 * a0.y + g1 * b0.y;
        rv.z = g0 * a1.x + g1 * b1.x;
        rv.w = g0 * a1.y + g1 * b1.y;
        o[i] = rv;
    }
}

// ---------------------------------------------------------------------------
// kernel_launch — single stream, no converts: GEMMs read fp32 weights.
// ---------------------------------------------------------------------------
extern "C" void kernel_launch(void* const* d_in, const int* in_sizes, int n_in,
                              void* d_out, int out_size) {
    const float* x  = (const float*)d_in[0];
    const float* Wg = (const float*)d_in[1];
    const float* W1 = (const float*)d_in[2];
    const float* b1 = (const float*)d_in[3];
    const float* W2 = (const float*)d_in[4];
    const float* b2 = (const float*)d_in[5];
    float* out = (float*)d_out;

    void *xe_p, *h_p, *ye_p;
    cudaGetSymbolAddress(&xe_p, g_Xe);
    cudaGetSymbolAddress(&h_p,  g_h);
    cudaGetSymbolAddress(&ye_p, g_Ye);

    cudaFuncSetAttribute(gemm_hmma<D_DIM, FF_DIM, true >,
                         cudaFuncAttributeMaxDynamicSharedMemorySize, GEMM_SMEM);
    cudaFuncSetAttribute(gemm_hmma<FF_DIM, D_DIM, false>,
                         cudaFuncAttributeMaxDynamicSharedMemorySize, GEMM_SMEM);

    gate_kernel<<<T_TOK / 8, 256>>>(x, Wg);
    scan_kernel<<<E_EXP, 256>>>();
    dispatch_kernel<<<T_TOK, 256>>>(x);

    gemm_hmma<D_DIM, FF_DIM, true ><<<dim3(CAP / 128, FF_DIM / 128, E_EXP),
                                      256, GEMM_SMEM>>>(
        (const __half*)xe_p, W1, b1, (__half*)h_p);

    gemm_hmma<FF_DIM, D_DIM, false><<<dim3(CAP / 128, D_DIM / 128, E_EXP),
                                      256, GEMM_SMEM>>>(
        (const __half*)h_p, W2, b2, (__half*)ye_p);

    combine_kernel<<<T_TOK, 256>>>(out);
}